// round 7
// baseline (speedup 1.0000x reference)
#include <cuda_runtime.h>
#include <cuda_bf16.h>
#include <cstdint>
#include <cstddef>

// Problem constants
#define N_NODES 50000
#define N_PAD   50048
#define KNBR    32
#define FDIM    128
#define EDIM    8
#define KDIM    1024          // FDIM * EDIM

// G split into bf16 hi/lo, rows [i][kk], kk = n*128 + l
// (__device__ globals are zero-initialized; padded rows [50000,50048) are
//  never written and thus read back as zeros in phase B.)
__device__ __nv_bfloat16 g_hi[(size_t)N_PAD * KDIM];   // 102.5 MB
__device__ __nv_bfloat16 g_lo[(size_t)N_PAD * KDIM];   // 102.5 MB
// W rearranged to [kk][m] bf16 hi/lo
__device__ __nv_bfloat16 wt_hi[KDIM * FDIM];
__device__ __nv_bfloat16 wt_lo[KDIM * FDIM];
// nlist dtype flag: 1 = int64 storage, 0 = int32 storage
__device__ int g_nlist_is64;

// ---------------------------------------------------------------------------
// helpers
// ---------------------------------------------------------------------------
__device__ __forceinline__ uint32_t smem_u32(const void* p) {
    uint32_t a;
    asm("{ .reg .u64 t; cvta.to.shared.u64 t, %1; cvt.u32.u64 %0, t; }" : "=r"(a) : "l"(p));
    return a;
}

__device__ __forceinline__ void cp_async16(uint32_t dst, const void* src) {
    asm volatile("cp.async.cg.shared.global [%0], [%1], 16;" :: "r"(dst), "l"(src));
}
__device__ __forceinline__ void cp_commit() {
    asm volatile("cp.async.commit_group;");
}

__device__ __forceinline__ void ldm_x4(uint32_t* r, uint32_t addr) {
    asm volatile("ldmatrix.sync.aligned.m8n8.x4.shared.b16 {%0,%1,%2,%3}, [%4];"
                 : "=r"(r[0]), "=r"(r[1]), "=r"(r[2]), "=r"(r[3]) : "r"(addr));
}
__device__ __forceinline__ void ldm_x4t(uint32_t* r, uint32_t addr) {
    asm volatile("ldmatrix.sync.aligned.m8n8.x4.trans.shared.b16 {%0,%1,%2,%3}, [%4];"
                 : "=r"(r[0]), "=r"(r[1]), "=r"(r[2]), "=r"(r[3]) : "r"(addr));
}

__device__ __forceinline__ void mma_bf16(float* c, const uint32_t* a, const uint32_t* b) {
    asm volatile(
        "mma.sync.aligned.m16n8k16.row.col.f32.bf16.bf16.f32 "
        "{%0,%1,%2,%3}, {%4,%5,%6,%7}, {%8,%9}, {%0,%1,%2,%3};"
        : "+f"(c[0]), "+f"(c[1]), "+f"(c[2]), "+f"(c[3])
        : "r"(a[0]), "r"(a[1]), "r"(a[2]), "r"(a[3]), "r"(b[0]), "r"(b[1]));
}

__device__ __forceinline__ void fma4(float4& a, float s, const float4& x) {
    a.x = fmaf(s, x.x, a.x);
    a.y = fmaf(s, x.y, a.y);
    a.z = fmaf(s, x.z, a.z);
    a.w = fmaf(s, x.w, a.w);
}

// ---------------------------------------------------------------------------
// Kernel -1: detect nlist element width (odd 32-bit words all-zero => int64)
// ---------------------------------------------------------------------------
__global__ void detect_nlist_kernel(const unsigned int* __restrict__ nl) {
    const int lane = threadIdx.x;
    unsigned int acc = 0;
#pragma unroll
    for (int k = 0; k < 32; k++)
        acc |= nl[1 + 2 * (lane + 32 * k)];
#pragma unroll
    for (int o = 16; o > 0; o >>= 1)
        acc |= __shfl_xor_sync(0xffffffffu, acc, o);
    if (lane == 0) g_nlist_is64 = (acc == 0u) ? 1 : 0;
}

// ---------------------------------------------------------------------------
// Kernel 0: w (F,F,E) -> wt_hi/wt_lo [kk][m],  kk = n*128 + l
// ---------------------------------------------------------------------------
__global__ void transpose_w_kernel(const float* __restrict__ w) {
    int idx = blockIdx.x * blockDim.x + threadIdx.x;
    if (idx >= KDIM * FDIM) return;
    int kk = idx >> 7;          // n*128 + l
    int m  = idx & 127;
    int n  = kk >> 7;
    int l  = kk & 127;
    float v = w[(l * FDIM + m) * EDIM + n];
    __nv_bfloat16 hi = __float2bfloat16_rn(v);
    __nv_bfloat16 lo = __float2bfloat16_rn(v - __bfloat162float(hi));
    wt_hi[idx] = hi;
    wt_lo[idx] = lo;
}

// ---------------------------------------------------------------------------
// FUSED kernel: phase A (gather-contract -> G hi/lo for own 128 rows)
//             + phase B (mma.sync bf16 split GEMM on own rows)
// Dependency is tile-local, so no grid sync is needed: each CTA consumes only
// the G rows it produced itself (ordering via st.global -> __syncthreads ->
// cp.async, all L2-coherent).
// ---------------------------------------------------------------------------
#define KC        32
#define NKCHUNKS  (KDIM / KC)         // 32
#define BUF_BYTES 32768               // Ahi|Alo|Bhi|Blo
#define OFF_AHI   0
#define OFF_ALO   8192
#define OFF_BHI   16384
#define OFF_BLO   24576
#define NSTAGES   3
#define SMEM_DYN  (NSTAGES * BUF_BYTES)

__global__ void __launch_bounds__(256, 2) fused_kernel(
    const float* __restrict__ nodes,
    const void* __restrict__ nlist,
    const float* __restrict__ edges,
    const float* __restrict__ inv_degree,
    float* __restrict__ out)
{
    extern __shared__ __align__(128) char smem[];
    const uint32_t sbase = smem_u32(smem);

    const int tid    = threadIdx.x;
    const int lane   = tid & 31;
    const int wid    = tid >> 5;
    const int m0     = blockIdx.x * 128;

    // ======================= PHASE A: gather-contract =======================
    // 8 warps; warp handles 16 nodes sequentially. Staging aliases the (not
    // yet used) pipeline smem: per-warp 1280 B = 32 idx + 256 edge floats.
    {
        int*   nb_w = (int*)  (smem + wid * 1280);
        float* e_w  = (float*)(smem + wid * 1280 + 128);
        const int is64 = g_nlist_is64;

#pragma unroll 1
        for (int it = 0; it < 16; it++) {
            const int i = m0 + wid * 16 + it;      // warp-uniform
            if (i < N_NODES) {
                // neighbor indices (dtype-agnostic) + defensive clamp
                const size_t nidx = (size_t)i * KNBR + lane;
                int nbi;
                if (is64) nbi = (int)((const long long*)nlist)[nidx];
                else      nbi = ((const int*)nlist)[nidx];
                nbi = nbi < 0 ? 0 : (nbi >= N_NODES ? N_NODES - 1 : nbi);
                nb_w[lane] = nbi;

                // edges row: lane owns floats [lane*8, lane*8+8)
                const float4* e4 = (const float4*)(edges + (size_t)i * (KNBR * EDIM));
                ((float4*)e_w)[lane * 2 + 0] = e4[lane * 2 + 0];
                ((float4*)e_w)[lane * 2 + 1] = e4[lane * 2 + 1];
                __syncwarp();

                float4 acc[EDIM];
#pragma unroll
                for (int n = 0; n < EDIM; n++) acc[n] = make_float4(0.f, 0.f, 0.f, 0.f);

#pragma unroll 8
                for (int j = 0; j < KNBR; j++) {
                    const int nb = nb_w[j];
                    const float4 x = *(const float4*)(nodes + (size_t)nb * FDIM + lane * 4);
                    const float4 e0 = *(const float4*)&e_w[j * 8 + 0];
                    const float4 e1 = *(const float4*)&e_w[j * 8 + 4];
                    fma4(acc[0], e0.x, x);
                    fma4(acc[1], e0.y, x);
                    fma4(acc[2], e0.z, x);
                    fma4(acc[3], e0.w, x);
                    fma4(acc[4], e1.x, x);
                    fma4(acc[5], e1.y, x);
                    fma4(acc[6], e1.z, x);
                    fma4(acc[7], e1.w, x);
                }

                const size_t rbase = (size_t)i * KDIM + lane * 4;
#pragma unroll
                for (int n = 0; n < EDIM; n++) {
                    float v0 = acc[n].x, v1 = acc[n].y, v2 = acc[n].z, v3 = acc[n].w;
                    __nv_bfloat16 h0 = __float2bfloat16_rn(v0);
                    __nv_bfloat16 h1 = __float2bfloat16_rn(v1);
                    __nv_bfloat16 h2 = __float2bfloat16_rn(v2);
                    __nv_bfloat16 h3 = __float2bfloat16_rn(v3);
                    __nv_bfloat16 l0 = __float2bfloat16_rn(v0 - __bfloat162float(h0));
                    __nv_bfloat16 l1 = __float2bfloat16_rn(v1 - __bfloat162float(h1));
                    __nv_bfloat16 l2 = __float2bfloat16_rn(v2 - __bfloat162float(h2));
                    __nv_bfloat16 l3 = __float2bfloat16_rn(v3 - __bfloat162float(h3));
                    __nv_bfloat162 hA = __nv_bfloat162(h0, h1), hB = __nv_bfloat162(h2, h3);
                    __nv_bfloat162 lA = __nv_bfloat162(l0, l1), lB = __nv_bfloat162(l2, l3);
                    *(uint2*)&g_hi[rbase + n * FDIM] = make_uint2(*(uint32_t*)&hA, *(uint32_t*)&hB);
                    *(uint2*)&g_lo[rbase + n * FDIM] = make_uint2(*(uint32_t*)&lA, *(uint32_t*)&lB);
                }
                __syncwarp();
            }
        }
    }

    __syncthreads();   // phase A stores done; smem staging dead; start GEMM

    // ======================= PHASE B: tensor GEMM ===========================
    const int warp_m = wid & 3;        // m offset 32*warp_m
    const int warp_n = wid >> 2;       // n offset 64*warp_n

    float acc[2][8][4];
#pragma unroll
    for (int mt = 0; mt < 2; mt++)
#pragma unroll
        for (int nt = 0; nt < 8; nt++)
#pragma unroll
            for (int q = 0; q < 4; q++) acc[mt][nt][q] = 0.f;

    auto load_chunk = [&](int kc, int b) {
        if (kc < NKCHUNKS) {
            const uint32_t sb = sbase + b * BUF_BYTES;
#pragma unroll
            for (int it = 0; it < 2; it++) {
                const int ca  = tid + it * 256;
                const int row = ca >> 2;
                const int c   = ca & 3;
                const uint32_t so = row * 64 + ((c ^ ((row >> 1) & 3)) << 4);
                const size_t ge = (size_t)(m0 + row) * KDIM + kc * KC + c * 8;
                cp_async16(sb + OFF_AHI + so, g_hi + ge);
                cp_async16(sb + OFF_ALO + so, g_lo + ge);
            }
#pragma unroll
            for (int it = 0; it < 2; it++) {
                const int cb  = tid + it * 256;
                const int row = cb >> 4;
                const int c   = cb & 15;
                const uint32_t so = row * 256 + ((c ^ (row & 15)) << 4);
                const size_t ge = (size_t)(kc * KC + row) * FDIM + c * 8;
                cp_async16(sb + OFF_BHI + so, wt_hi + ge);
                cp_async16(sb + OFF_BLO + so, wt_lo + ge);
            }
        }
        cp_commit();
    };

    load_chunk(0, 0);
    load_chunk(1, 1);

#pragma unroll 1
    for (int kc = 0; kc < NKCHUNKS; kc++) {
        asm volatile("cp.async.wait_group 1;");
        __syncthreads();

        load_chunk(kc + 2, (kc + 2) % NSTAGES);

        const uint32_t sb = sbase + (kc % NSTAGES) * BUF_BYTES;

#pragma unroll
        for (int k16 = 0; k16 < 2; k16++) {
            uint32_t ahi[2][4], alo[2][4];
            const int rA   = (lane & 7) + ((lane >> 3) & 1) * 8;
            const int kch  = k16 * 2 + (lane >> 4);
#pragma unroll
            for (int mt = 0; mt < 2; mt++) {
                const int row = warp_m * 32 + mt * 16 + rA;
                const uint32_t off = row * 64 + ((kch ^ ((row >> 1) & 3)) << 4);
                ldm_x4(ahi[mt], sb + OFF_AHI + off);
                ldm_x4(alo[mt], sb + OFF_ALO + off);
            }
            const int rB = k16 * 16 + (lane & 7) + ((lane >> 3) & 1) * 8;
#pragma unroll
            for (int nt16 = 0; nt16 < 4; nt16++) {
                const int nch = warp_n * 8 + nt16 * 2 + (lane >> 4);
                const uint32_t off = rB * 256 + ((nch ^ (rB & 15)) << 4);
                uint32_t bhi[4], blo[4];
                ldm_x4t(bhi, sb + OFF_BHI + off);
                ldm_x4t(blo, sb + OFF_BLO + off);
#pragma unroll
                for (int mt = 0; mt < 2; mt++) {
                    mma_bf16(acc[mt][nt16 * 2 + 0], ahi[mt], bhi + 0);
                    mma_bf16(acc[mt][nt16 * 2 + 1], ahi[mt], bhi + 2);
                    mma_bf16(acc[mt][nt16 * 2 + 0], ahi[mt], blo + 0);
                    mma_bf16(acc[mt][nt16 * 2 + 1], ahi[mt], blo + 2);
                    mma_bf16(acc[mt][nt16 * 2 + 0], alo[mt], bhi + 0);
                    mma_bf16(acc[mt][nt16 * 2 + 1], alo[mt], bhi + 2);
                }
            }
        }
    }

    // ---- epilogue: scale + store ----
#pragma unroll
    for (int mt = 0; mt < 2; mt++) {
        const int r0 = m0 + warp_m * 32 + mt * 16 + (lane >> 2);
        const int r1 = r0 + 8;
        const float s0 = (r0 < N_NODES) ? inv_degree[r0] : 0.f;
        const float s1 = (r1 < N_NODES) ? inv_degree[r1] : 0.f;
#pragma unroll
        for (int nt = 0; nt < 8; nt++) {
            const int col = warp_n * 64 + nt * 8 + (lane & 3) * 2;
            if (r0 < N_NODES) {
                float2 o = make_float2(acc[mt][nt][0] * s0, acc[mt][nt][1] * s0);
                *(float2*)(out + (size_t)r0 * FDIM + col) = o;
            }
            if (r1 < N_NODES) {
                float2 o = make_float2(acc[mt][nt][2] * s1, acc[mt][nt][3] * s1);
                *(float2*)(out + (size_t)r1 * FDIM + col) = o;
            }
        }
    }
}

// ---------------------------------------------------------------------------
// Launch. Inputs identified BY ELEMENT COUNT (all five distinct).
// ---------------------------------------------------------------------------
extern "C" void kernel_launch(void* const* d_in, const int* in_sizes, int n_in,
                              void* d_out, int out_size) {
    const float* nodes      = nullptr;
    const void*  nlist      = nullptr;
    const float* edges      = nullptr;
    const float* inv_degree = nullptr;
    const float* w          = nullptr;

    for (int i = 0; i < n_in; i++) {
        switch (in_sizes[i]) {
            case 6400000:  nodes      = (const float*)d_in[i]; break;
            case 1600000:  nlist      = d_in[i];               break;
            case 3200000:  nlist      = d_in[i];               break;
            case 12800000: edges      = (const float*)d_in[i]; break;
            case 50000:    inv_degree = (const float*)d_in[i]; break;
            case 131072:   w          = (const float*)d_in[i]; break;
            default: break;
        }
    }
    if (!nodes || !nlist || !edges || !inv_degree || !w) return;

    float* out = (float*)d_out;

    cudaFuncSetAttribute(fused_kernel,
                         cudaFuncAttributeMaxDynamicSharedMemorySize, SMEM_DYN);

    detect_nlist_kernel<<<1, 32>>>((const unsigned int*)nlist);
    transpose_w_kernel<<<(KDIM * FDIM + 255) / 256, 256>>>(w);
    fused_kernel<<<(N_NODES + 127) / 128, 256, SMEM_DYN>>>(
        nodes, nlist, edges, inv_degree, out);
}

// round 9
// speedup vs baseline: 1.1365x; 1.1365x over previous
#include <cuda_runtime.h>
#include <cuda_bf16.h>
#include <cstdint>
#include <cstddef>

// Problem constants
#define N_NODES 50000
#define N_PAD   50048
#define KNBR    32
#define FDIM    128
#define EDIM    8
#define KDIM    1024          // FDIM * EDIM

// G split into bf16 hi/lo, rows [i][kk], kk = n*128 + l
// (__device__ globals zero-init; padded rows [50000,50048) stay zero.)
__device__ __nv_bfloat16 g_hi[(size_t)N_PAD * KDIM];   // 102.5 MB
__device__ __nv_bfloat16 g_lo[(size_t)N_PAD * KDIM];   // 102.5 MB
// W rearranged to [kk][m] bf16 hi/lo
__device__ __nv_bfloat16 wt_hi[KDIM * FDIM];
__device__ __nv_bfloat16 wt_lo[KDIM * FDIM];

// ---------------------------------------------------------------------------
// helpers
// ---------------------------------------------------------------------------
__device__ __forceinline__ uint32_t smem_u32(const void* p) {
    uint32_t a;
    asm("{ .reg .u64 t; cvta.to.shared.u64 t, %1; cvt.u32.u64 %0, t; }" : "=r"(a) : "l"(p));
    return a;
}

__device__ __forceinline__ void cp_async16(uint32_t dst, const void* src) {
    asm volatile("cp.async.cg.shared.global [%0], [%1], 16;" :: "r"(dst), "l"(src));
}
__device__ __forceinline__ void cp_commit() {
    asm volatile("cp.async.commit_group;");
}

__device__ __forceinline__ void ldm_x4(uint32_t* r, uint32_t addr) {
    asm volatile("ldmatrix.sync.aligned.m8n8.x4.shared.b16 {%0,%1,%2,%3}, [%4];"
                 : "=r"(r[0]), "=r"(r[1]), "=r"(r[2]), "=r"(r[3]) : "r"(addr));
}
__device__ __forceinline__ void ldm_x4t(uint32_t* r, uint32_t addr) {
    asm volatile("ldmatrix.sync.aligned.m8n8.x4.trans.shared.b16 {%0,%1,%2,%3}, [%4];"
                 : "=r"(r[0]), "=r"(r[1]), "=r"(r[2]), "=r"(r[3]) : "r"(addr));
}

__device__ __forceinline__ void mma_bf16(float* c, const uint32_t* a, const uint32_t* b) {
    asm volatile(
        "mma.sync.aligned.m16n8k16.row.col.f32.bf16.bf16.f32 "
        "{%0,%1,%2,%3}, {%4,%5,%6,%7}, {%8,%9}, {%0,%1,%2,%3};"
        : "+f"(c[0]), "+f"(c[1]), "+f"(c[2]), "+f"(c[3])
        : "r"(a[0]), "r"(a[1]), "r"(a[2]), "r"(a[3]), "r"(b[0]), "r"(b[1]));
}

__device__ __forceinline__ void fma4(float4& a, float s, const float4& x) {
    a.x = fmaf(s, x.x, a.x);
    a.y = fmaf(s, x.y, a.y);
    a.z = fmaf(s, x.z, a.z);
    a.w = fmaf(s, x.w, a.w);
}

// ---------------------------------------------------------------------------
// Kernel 0: w (F,F,E) -> wt_hi/wt_lo [kk][m],  kk = n*128 + l
// ---------------------------------------------------------------------------
__global__ void transpose_w_kernel(const float* __restrict__ w) {
    int idx = blockIdx.x * blockDim.x + threadIdx.x;
    if (idx >= KDIM * FDIM) return;
    int kk = idx >> 7;          // n*128 + l
    int m  = idx & 127;
    int n  = kk >> 7;
    int l  = kk & 127;
    float v = w[(l * FDIM + m) * EDIM + n];
    __nv_bfloat16 hi = __float2bfloat16_rn(v);
    __nv_bfloat16 lo = __float2bfloat16_rn(v - __bfloat162float(hi));
    wt_hi[idx] = hi;
    wt_lo[idx] = lo;
}

// ---------------------------------------------------------------------------
// Kernel 1: stage 1 — G row, written as bf16 hi/lo split
// One warp per node i. Lane owns l = lane*4..lane*4+3.
// nlist is int32 (proven: int64-width reads fault; int32 passes).
// ---------------------------------------------------------------------------
__global__ void __launch_bounds__(256) stage1_kernel(
    const float* __restrict__ nodes,
    const int* __restrict__ nlist,
    const float* __restrict__ edges)
{
    __shared__ int   s_nb[8][KNBR];
    __shared__ float s_e[8][KNBR * EDIM];

    const int warp = threadIdx.x >> 5;
    const int lane = threadIdx.x & 31;
    const int i = blockIdx.x * 8 + warp;

    int nbi = nlist[(size_t)i * KNBR + lane];
    nbi = nbi < 0 ? 0 : (nbi >= N_NODES ? N_NODES - 1 : nbi);   // safety clamp
    s_nb[warp][lane] = nbi;

    const float4* e4 = (const float4*)(edges + (size_t)i * (KNBR * EDIM));
    float4* se4 = (float4*)s_e[warp];
    se4[lane * 2 + 0] = e4[lane * 2 + 0];
    se4[lane * 2 + 1] = e4[lane * 2 + 1];
    __syncwarp();

    float4 acc[EDIM];
#pragma unroll
    for (int n = 0; n < EDIM; n++) acc[n] = make_float4(0.f, 0.f, 0.f, 0.f);

#pragma unroll 4
    for (int j = 0; j < KNBR; j++) {
        const int nb = s_nb[warp][j];
        const float4 x = *(const float4*)(nodes + (size_t)nb * FDIM + lane * 4);
        const float4 e0 = *(const float4*)&s_e[warp][j * 8 + 0];
        const float4 e1 = *(const float4*)&s_e[warp][j * 8 + 4];
        fma4(acc[0], e0.x, x);
        fma4(acc[1], e0.y, x);
        fma4(acc[2], e0.z, x);
        fma4(acc[3], e0.w, x);
        fma4(acc[4], e1.x, x);
        fma4(acc[5], e1.y, x);
        fma4(acc[6], e1.z, x);
        fma4(acc[7], e1.w, x);
    }

    const size_t rbase = (size_t)i * KDIM + lane * 4;
#pragma unroll
    for (int n = 0; n < EDIM; n++) {
        float v0 = acc[n].x, v1 = acc[n].y, v2 = acc[n].z, v3 = acc[n].w;
        __nv_bfloat16 h0 = __float2bfloat16_rn(v0);
        __nv_bfloat16 h1 = __float2bfloat16_rn(v1);
        __nv_bfloat16 h2 = __float2bfloat16_rn(v2);
        __nv_bfloat16 h3 = __float2bfloat16_rn(v3);
        __nv_bfloat16 l0 = __float2bfloat16_rn(v0 - __bfloat162float(h0));
        __nv_bfloat16 l1 = __float2bfloat16_rn(v1 - __bfloat162float(h1));
        __nv_bfloat16 l2 = __float2bfloat16_rn(v2 - __bfloat162float(h2));
        __nv_bfloat16 l3 = __float2bfloat16_rn(v3 - __bfloat162float(h3));
        __nv_bfloat162 hA = __nv_bfloat162(h0, h1), hB = __nv_bfloat162(h2, h3);
        __nv_bfloat162 lA = __nv_bfloat162(l0, l1), lB = __nv_bfloat162(l2, l3);
        *(uint2*)&g_hi[rbase + n * FDIM] = make_uint2(*(uint32_t*)&hA, *(uint32_t*)&hB);
        *(uint2*)&g_lo[rbase + n * FDIM] = make_uint2(*(uint32_t*)&lA, *(uint32_t*)&lB);
    }
}

// ---------------------------------------------------------------------------
// Kernel 2: mma.sync bf16 split GEMM, BM=64 x BN=128, 3-stage cp.async,
// 3 CTAs/SM (finer tiles kill the 2-wave quantization of BM=128).
//   out[i,m] = inv_degree[i] * sum_kk (Ghi+Glo)[i,kk] * (Whi+Wlo)[kk,m]
//   (lo*lo dropped)
// 8 warps (4m x 2n), warp tile 16x64.
// Smem swizzles:
//   A tile [64][32] bf16  (64B rows, 4 chunks):  chunk' = c ^ ((row>>1)&3)
//   B tile [32][128] bf16 (256B rows, 16 chunks): chunk' = c ^ (row&15)
// ---------------------------------------------------------------------------
#define BM        64
#define KC        32
#define NKCHUNKS  (KDIM / KC)         // 32
#define OFF_AHI   0
#define OFF_ALO   4096
#define OFF_BHI   8192
#define OFF_BLO   16384
#define BUF_BYTES 24576               // 4K+4K+8K+8K
#define NSTAGES   3
#define SMEM_DYN  (NSTAGES * BUF_BYTES)   // 72 KB

__global__ void __launch_bounds__(256, 3) stage2_mma_kernel(
    const float* __restrict__ inv_degree,
    float* __restrict__ out)
{
    extern __shared__ __align__(128) char smem[];
    const uint32_t sbase = smem_u32(smem);

    const int tid    = threadIdx.x;
    const int lane   = tid & 31;
    const int wid    = tid >> 5;
    const int warp_m = wid & 3;        // m offset 16*warp_m
    const int warp_n = wid >> 2;       // n offset 64*warp_n
    const int m0     = blockIdx.x * BM;

    float acc[8][4];
#pragma unroll
    for (int nt = 0; nt < 8; nt++)
#pragma unroll
        for (int q = 0; q < 4; q++) acc[nt][q] = 0.f;

    // ---- async load of one K-chunk into stage buffer b; always commits ----
    auto load_chunk = [&](int kc, int b) {
        if (kc < NKCHUNKS) {
            const uint32_t sb = sbase + b * BUF_BYTES;
            // A: 64 rows x 32 cols = 256 x 16B chunks per dtype (1 per thread)
            {
                const int row = tid >> 2;
                const int c   = tid & 3;
                const uint32_t so = row * 64 + ((c ^ ((row >> 1) & 3)) << 4);
                const size_t ge = (size_t)(m0 + row) * KDIM + kc * KC + c * 8;
                cp_async16(sb + OFF_AHI + so, g_hi + ge);
                cp_async16(sb + OFF_ALO + so, g_lo + ge);
            }
            // B: 32 rows x 128 cols = 512 x 16B chunks per dtype (2 per thread)
#pragma unroll
            for (int it = 0; it < 2; it++) {
                const int cb  = tid + it * 256;
                const int row = cb >> 4;
                const int c   = cb & 15;
                const uint32_t so = row * 256 + ((c ^ (row & 15)) << 4);
                const size_t ge = (size_t)(kc * KC + row) * FDIM + c * 8;
                cp_async16(sb + OFF_BHI + so, wt_hi + ge);
                cp_async16(sb + OFF_BLO + so, wt_lo + ge);
            }
        }
        cp_commit();
    };

    load_chunk(0, 0);
    load_chunk(1, 1);

#pragma unroll 1
    for (int kc = 0; kc < NKCHUNKS; kc++) {
        asm volatile("cp.async.wait_group 1;");
        __syncthreads();

        load_chunk(kc + 2, (kc + 2) % NSTAGES);

        const uint32_t sb = sbase + (kc % NSTAGES) * BUF_BYTES;

#pragma unroll
        for (int k16 = 0; k16 < 2; k16++) {
            // A fragments (one m16 tile, hi+lo)
            uint32_t ahi[4], alo[4];
            const int rA   = (lane & 7) + ((lane >> 3) & 1) * 8;
            const int kch  = k16 * 2 + (lane >> 4);
            {
                const int row = warp_m * 16 + rA;
                const uint32_t off = row * 64 + ((kch ^ ((row >> 1) & 3)) << 4);
                ldm_x4(ahi, sb + OFF_AHI + off);
                ldm_x4(alo, sb + OFF_ALO + off);
            }
            const int rB = k16 * 16 + (lane & 7) + ((lane >> 3) & 1) * 8;
#pragma unroll
            for (int nt16 = 0; nt16 < 4; nt16++) {
                const int nch = warp_n * 8 + nt16 * 2 + (lane >> 4);
                const uint32_t off = rB * 256 + ((nch ^ (rB & 15)) << 4);
                uint32_t bhi[4], blo[4];
                ldm_x4t(bhi, sb + OFF_BHI + off);
                ldm_x4t(blo, sb + OFF_BLO + off);
                mma_bf16(acc[nt16 * 2 + 0], ahi, bhi + 0);
                mma_bf16(acc[nt16 * 2 + 1], ahi, bhi + 2);
                mma_bf16(acc[nt16 * 2 + 0], ahi, blo + 0);
                mma_bf16(acc[nt16 * 2 + 1], ahi, blo + 2);
                mma_bf16(acc[nt16 * 2 + 0], alo, bhi + 0);
                mma_bf16(acc[nt16 * 2 + 1], alo, bhi + 2);
            }
        }
    }

    // ---- epilogue: scale + store ----
    {
        const int r0 = m0 + warp_m * 16 + (lane >> 2);
        const int r1 = r0 + 8;
        const float s0 = (r0 < N_NODES) ? inv_degree[r0] : 0.f;
        const float s1 = (r1 < N_NODES) ? inv_degree[r1] : 0.f;
#pragma unroll
        for (int nt = 0; nt < 8; nt++) {
            const int col = warp_n * 64 + nt * 8 + (lane & 3) * 2;
            if (r0 < N_NODES) {
                float2 o = make_float2(acc[nt][0] * s0, acc[nt][1] * s0);
                *(float2*)(out + (size_t)r0 * FDIM + col) = o;
            }
            if (r1 < N_NODES) {
                float2 o = make_float2(acc[nt][2] * s1, acc[nt][3] * s1);
                *(float2*)(out + (size_t)r1 * FDIM + col) = o;
            }
        }
    }
}

// ---------------------------------------------------------------------------
// Launch. Inputs identified BY ELEMENT COUNT (all five distinct).
// ---------------------------------------------------------------------------
extern "C" void kernel_launch(void* const* d_in, const int* in_sizes, int n_in,
                              void* d_out, int out_size) {
    const float* nodes      = nullptr;
    const int*   nlist      = nullptr;
    const float* edges      = nullptr;
    const float* inv_degree = nullptr;
    const float* w          = nullptr;

    for (int i = 0; i < n_in; i++) {
        switch (in_sizes[i]) {
            case 6400000:  nodes      = (const float*)d_in[i]; break;
            case 1600000:  nlist      = (const int*)d_in[i];   break;
            case 12800000: edges      = (const float*)d_in[i]; break;
            case 50000:    inv_degree = (const float*)d_in[i]; break;
            case 131072:   w          = (const float*)d_in[i]; break;
            default: break;
        }
    }
    if (!nodes || !nlist || !edges || !inv_degree || !w) return;

    float* out = (float*)d_out;

    cudaFuncSetAttribute(stage2_mma_kernel,
                         cudaFuncAttributeMaxDynamicSharedMemorySize, SMEM_DYN);

    transpose_w_kernel<<<(KDIM * FDIM + 255) / 256, 256>>>(w);
    stage1_kernel<<<N_NODES / 8, 256>>>(nodes, nlist, edges);
    stage2_mma_kernel<<<(N_NODES + BM - 1) / BM, 256, SMEM_DYN>>>(inv_degree, out);
}

// round 10
// speedup vs baseline: 1.7129x; 1.5071x over previous
#include <cuda_runtime.h>
#include <cuda_fp16.h>
#include <cstdint>
#include <cstddef>

// Problem constants
#define N_NODES 50000
#define N_PAD   50048
#define KNBR    32
#define FDIM    128
#define EDIM    8
#define KDIM    1024          // FDIM * EDIM

// G as fp16, rows [i][kk], kk = n*128 + l
// (__device__ globals zero-init; padded rows [50000,50048) stay zero.)
__device__ __half g_h[(size_t)N_PAD * KDIM];   // 102.5 MB
// W rearranged to [kk][m] fp16
__device__ __half wt_h[KDIM * FDIM];

// ---------------------------------------------------------------------------
// helpers
// ---------------------------------------------------------------------------
__device__ __forceinline__ uint32_t smem_u32(const void* p) {
    uint32_t a;
    asm("{ .reg .u64 t; cvta.to.shared.u64 t, %1; cvt.u32.u64 %0, t; }" : "=r"(a) : "l"(p));
    return a;
}

__device__ __forceinline__ void cp_async16(uint32_t dst, const void* src) {
    asm volatile("cp.async.cg.shared.global [%0], [%1], 16;" :: "r"(dst), "l"(src));
}
__device__ __forceinline__ void cp_commit() {
    asm volatile("cp.async.commit_group;");
}

__device__ __forceinline__ void ldm_x4(uint32_t* r, uint32_t addr) {
    asm volatile("ldmatrix.sync.aligned.m8n8.x4.shared.b16 {%0,%1,%2,%3}, [%4];"
                 : "=r"(r[0]), "=r"(r[1]), "=r"(r[2]), "=r"(r[3]) : "r"(addr));
}
__device__ __forceinline__ void ldm_x4t(uint32_t* r, uint32_t addr) {
    asm volatile("ldmatrix.sync.aligned.m8n8.x4.trans.shared.b16 {%0,%1,%2,%3}, [%4];"
                 : "=r"(r[0]), "=r"(r[1]), "=r"(r[2]), "=r"(r[3]) : "r"(addr));
}

__device__ __forceinline__ void mma_f16(float* c, const uint32_t* a, const uint32_t* b) {
    asm volatile(
        "mma.sync.aligned.m16n8k16.row.col.f32.f16.f16.f32 "
        "{%0,%1,%2,%3}, {%4,%5,%6,%7}, {%8,%9}, {%0,%1,%2,%3};"
        : "+f"(c[0]), "+f"(c[1]), "+f"(c[2]), "+f"(c[3])
        : "r"(a[0]), "r"(a[1]), "r"(a[2]), "r"(a[3]), "r"(b[0]), "r"(b[1]));
}

__device__ __forceinline__ void fma4(float4& a, float s, const float4& x) {
    a.x = fmaf(s, x.x, a.x);
    a.y = fmaf(s, x.y, a.y);
    a.z = fmaf(s, x.z, a.z);
    a.w = fmaf(s, x.w, a.w);
}

// ---------------------------------------------------------------------------
// Kernel 0: w (F,F,E) -> wt_h [kk][m],  kk = n*128 + l
// ---------------------------------------------------------------------------
__global__ void transpose_w_kernel(const float* __restrict__ w) {
    int idx = blockIdx.x * blockDim.x + threadIdx.x;
    if (idx >= KDIM * FDIM) return;
    int kk = idx >> 7;          // n*128 + l
    int m  = idx & 127;
    int n  = kk >> 7;
    int l  = kk & 127;
    wt_h[idx] = __float2half_rn(w[(l * FDIM + m) * EDIM + n]);
}

// ---------------------------------------------------------------------------
// Kernel 1: stage 1 — G row, fp32 accumulate, store fp16
// One warp per node i. Lane owns l = lane*4..lane*4+3.
// nlist is int32 (proven on hardware).
// ---------------------------------------------------------------------------
__global__ void __launch_bounds__(256) stage1_kernel(
    const float* __restrict__ nodes,
    const int* __restrict__ nlist,
    const float* __restrict__ edges)
{
    __shared__ int   s_nb[8][KNBR];
    __shared__ float s_e[8][KNBR * EDIM];

    const int warp = threadIdx.x >> 5;
    const int lane = threadIdx.x & 31;
    const int i = blockIdx.x * 8 + warp;

    int nbi = nlist[(size_t)i * KNBR + lane];
    nbi = nbi < 0 ? 0 : (nbi >= N_NODES ? N_NODES - 1 : nbi);   // safety clamp
    s_nb[warp][lane] = nbi;

    const float4* e4 = (const float4*)(edges + (size_t)i * (KNBR * EDIM));
    float4* se4 = (float4*)s_e[warp];
    se4[lane * 2 + 0] = e4[lane * 2 + 0];
    se4[lane * 2 + 1] = e4[lane * 2 + 1];
    __syncwarp();

    float4 acc[EDIM];
#pragma unroll
    for (int n = 0; n < EDIM; n++) acc[n] = make_float4(0.f, 0.f, 0.f, 0.f);

#pragma unroll 4
    for (int j = 0; j < KNBR; j++) {
        const int nb = s_nb[warp][j];
        const float4 x = *(const float4*)(nodes + (size_t)nb * FDIM + lane * 4);
        const float4 e0 = *(const float4*)&s_e[warp][j * 8 + 0];
        const float4 e1 = *(const float4*)&s_e[warp][j * 8 + 4];
        fma4(acc[0], e0.x, x);
        fma4(acc[1], e0.y, x);
        fma4(acc[2], e0.z, x);
        fma4(acc[3], e0.w, x);
        fma4(acc[4], e1.x, x);
        fma4(acc[5], e1.y, x);
        fma4(acc[6], e1.z, x);
        fma4(acc[7], e1.w, x);
    }

    const size_t rbase = (size_t)i * KDIM + lane * 4;
#pragma unroll
    for (int n = 0; n < EDIM; n++) {
        __half2 a = __floats2half2_rn(acc[n].x, acc[n].y);
        __half2 b = __floats2half2_rn(acc[n].z, acc[n].w);
        *(uint2*)&g_h[rbase + n * FDIM] = make_uint2(*(uint32_t*)&a, *(uint32_t*)&b);
    }
}

// ---------------------------------------------------------------------------
// Kernel 2: mma.sync fp16 single-product GEMM, BM=64 x BN=128, 4-stage
// cp.async pipeline, 3 CTAs/SM.
//   out[i,m] = inv_degree[i] * sum_kk G[i,kk] * W[kk,m]   (fp16 x fp16 -> fp32)
// 8 warps (4m x 2n), warp tile 16x64.
// Smem swizzles:
//   A tile [64][32] fp16  (64B rows, 4 chunks):  chunk' = c ^ ((row>>1)&3)
//   B tile [32][128] fp16 (256B rows, 16 chunks): chunk' = c ^ (row&15)
// ---------------------------------------------------------------------------
#define BM        64
#define KC        32
#define NKCHUNKS  (KDIM / KC)         // 32
#define OFF_A     0
#define OFF_B     4096
#define BUF_BYTES 12288               // 4K (A) + 8K (B)
#define NSTAGES   4
#define SMEM_DYN  (NSTAGES * BUF_BYTES)   // 48 KB

__global__ void __launch_bounds__(256, 3) stage2_mma_kernel(
    const float* __restrict__ inv_degree,
    float* __restrict__ out)
{
    extern __shared__ __align__(128) char smem[];
    const uint32_t sbase = smem_u32(smem);

    const int tid    = threadIdx.x;
    const int lane   = tid & 31;
    const int wid    = tid >> 5;
    const int warp_m = wid & 3;        // m offset 16*warp_m
    const int warp_n = wid >> 2;       // n offset 64*warp_n
    const int m0     = blockIdx.x * BM;

    float acc[8][4];
#pragma unroll
    for (int nt = 0; nt < 8; nt++)
#pragma unroll
        for (int q = 0; q < 4; q++) acc[nt][q] = 0.f;

    // ---- async load of one K-chunk into stage buffer b; always commits ----
    auto load_chunk = [&](int kc, int b) {
        if (kc < NKCHUNKS) {
            const uint32_t sb = sbase + b * BUF_BYTES;
            // A: 64 rows x 32 cols fp16 = 256 x 16B chunks (1 per thread)
            {
                const int row = tid >> 2;
                const int c   = tid & 3;
                const uint32_t so = row * 64 + ((c ^ ((row >> 1) & 3)) << 4);
                const size_t ge = (size_t)(m0 + row) * KDIM + kc * KC + c * 8;
                cp_async16(sb + OFF_A + so, g_h + ge);
            }
            // B: 32 rows x 128 cols fp16 = 512 x 16B chunks (2 per thread)
#pragma unroll
            for (int it = 0; it < 2; it++) {
                const int cb  = tid + it * 256;
                const int row = cb >> 4;
                const int c   = cb & 15;
                const uint32_t so = row * 256 + ((c ^ (row & 15)) << 4);
                const size_t ge = (size_t)(kc * KC + row) * FDIM + c * 8;
                cp_async16(sb + OFF_B + so, wt_h + ge);
            }
        }
        cp_commit();
    };

    load_chunk(0, 0);
    load_chunk(1, 1);
    load_chunk(2, 2);

#pragma unroll 1
    for (int kc = 0; kc < NKCHUNKS; kc++) {
        asm volatile("cp.async.wait_group 2;");
        __syncthreads();

        load_chunk(kc + 3, (kc + 3) % NSTAGES);

        const uint32_t sb = sbase + (kc % NSTAGES) * BUF_BYTES;

#pragma unroll
        for (int k16 = 0; k16 < 2; k16++) {
            uint32_t af[4];
            const int rA   = (lane & 7) + ((lane >> 3) & 1) * 8;
            const int kch  = k16 * 2 + (lane >> 4);
            {
                const int row = warp_m * 16 + rA;
                const uint32_t off = row * 64 + ((kch ^ ((row >> 1) & 3)) << 4);
                ldm_x4(af, sb + OFF_A + off);
            }
            const int rB = k16 * 16 + (lane & 7) + ((lane >> 3) & 1) * 8;
#pragma unroll
            for (int nt16 = 0; nt16 < 4; nt16++) {
                const int nch = warp_n * 8 + nt16 * 2 + (lane >> 4);
                const uint32_t off = rB * 256 + ((nch ^ (rB & 15)) << 4);
                uint32_t bf[4];
                ldm_x4t(bf, sb + OFF_B + off);
                mma_f16(acc[nt16 * 2 + 0], af, bf + 0);
                mma_f16(acc[nt16 * 2 + 1], af, bf + 2);
            }
        }
    }

    // ---- epilogue: scale + store ----
    {
        const int r0 = m0 + warp_m * 16 + (lane >> 2);
        const int r1 = r0 + 8;
        const float s0 = (r0 < N_NODES) ? inv_degree[r0] : 0.f;
        const float s1 = (r1 < N_NODES) ? inv_degree[r1] : 0.f;
#pragma unroll
        for (int nt = 0; nt < 8; nt++) {
            const int col = warp_n * 64 + nt * 8 + (lane & 3) * 2;
            if (r0 < N_NODES) {
                float2 o = make_float2(acc[nt][0] * s0, acc[nt][1] * s0);
                *(float2*)(out + (size_t)r0 * FDIM + col) = o;
            }
            if (r1 < N_NODES) {
                float2 o = make_float2(acc[nt][2] * s1, acc[nt][3] * s1);
                *(float2*)(out + (size_t)r1 * FDIM + col) = o;
            }
        }
    }
}

// ---------------------------------------------------------------------------
// Launch. Inputs identified BY ELEMENT COUNT (all five distinct).
// ---------------------------------------------------------------------------
extern "C" void kernel_launch(void* const* d_in, const int* in_sizes, int n_in,
                              void* d_out, int out_size) {
    const float* nodes      = nullptr;
    const int*   nlist      = nullptr;
    const float* edges      = nullptr;
    const float* inv_degree = nullptr;
    const float* w          = nullptr;

    for (int i = 0; i < n_in; i++) {
        switch (in_sizes[i]) {
            case 6400000:  nodes      = (const float*)d_in[i]; break;
            case 1600000:  nlist      = (const int*)d_in[i];   break;
            case 12800000: edges      = (const float*)d_in[i]; break;
            case 50000:    inv_degree = (const float*)d_in[i]; break;
            case 131072:   w          = (const float*)d_in[i]; break;
            default: break;
        }
    }
    if (!nodes || !nlist || !edges || !inv_degree || !w) return;

    float* out = (float*)d_out;

    cudaFuncSetAttribute(stage2_mma_kernel,
                         cudaFuncAttributeMaxDynamicSharedMemorySize, SMEM_DYN);

    transpose_w_kernel<<<(KDIM * FDIM + 255) / 256, 256>>>(w);
    stage1_kernel<<<N_NODES / 8, 256>>>(nodes, nlist, edges);
    stage2_mma_kernel<<<(N_NODES + BM - 1) / BM, 256, SMEM_DYN>>>(inv_degree, out);
}